// round 3
// baseline (speedup 1.0000x reference)
#include <cuda_runtime.h>
#include <cmath>

// Problem constants
#define BB   64     // batch
#define SS   512    // seq
#define EE   256    // embed
#define HH   512    // hidden
#define GG   2048   // 4*H
#define NTOT 2560   // GG + HH (gate cols + W_d cols)

// Persistent-kernel geometry
#define NB    296   // blocks (2 per SM on 148 SMs)
#define NTHR  128
#define NT    40    // N tiles of 64 cols (2560/64)
#define KS    16    // K slices of 32 (512/32)
#define NTASK (NT * KS)   // 640 GEMM tasks per step

// ---------------- device scratch (static; no allocations allowed) ----------------
__device__ float g_uproj[(size_t)BB * SS * GG];          // 256 MB
__device__ float g_h[BB * HH];
__device__ float g_c[BB * HH];
__device__ float g_part[(size_t)KS * BB * NTOT];         // split-K partials, 10.5 MB

__device__ unsigned g_count = 0;   // barrier arrivals (self-resetting)
__device__ unsigned g_gen   = 0;   // barrier generation (monotonic)
__device__ unsigned g_task  = 0;   // work-steal counter (reset at kernel end)

// ---------------- grid-wide barrier (sense-reversing, replay-safe) ----------------
__device__ __forceinline__ void gsync() {
    __syncthreads();
    if (threadIdx.x == 0) {
        __threadfence();
        unsigned gen = *(volatile unsigned*)&g_gen;
        __threadfence();                       // order gen read before arrive
        if (atomicAdd(&g_count, 1u) == NB - 1u) {
            g_count = 0;                       // only last block writes
            __threadfence();
            atomicAdd(&g_gen, 1u);             // release
        } else {
            while (*(volatile unsigned*)&g_gen == gen) __nanosleep(64);
        }
        __threadfence();
    }
    __syncthreads();
}

// ---------------- u_proj GEMM: [32768 x 2048] = inputs @ U^T (+ U_b + W_all_b) ----------------
__global__ __launch_bounds__(256) void uproj_kernel(
    const float* __restrict__ inp,   // [B*S, E]
    const float* __restrict__ Uw,    // [G, E]
    const float* __restrict__ Ub,    // [G]
    const float* __restrict__ Wab)   // [G]
{
    __shared__ float As[16][132];
    __shared__ float Bs[16][132];

    const int bm = blockIdx.x;
    const int bn = blockIdx.y;
    const int tid = threadIdx.x;
    const int tx = tid & 15;
    const int ty = tid >> 4;

    float acc[8][8];
#pragma unroll
    for (int i = 0; i < 8; i++)
#pragma unroll
        for (int j = 0; j < 8; j++) acc[i][j] = 0.0f;

    const int m0 = bm * 128;
    const int n0 = bn * 128;

    for (int k0 = 0; k0 < EE; k0 += 16) {
#pragma unroll
        for (int i = 0; i < 2; i++) {
            int idx = tid + i * 256;
            int row = idx >> 2;
            int kq  = (idx & 3) << 2;
            float4 v = *reinterpret_cast<const float4*>(inp + (size_t)(m0 + row) * EE + k0 + kq);
            As[kq + 0][row] = v.x; As[kq + 1][row] = v.y;
            As[kq + 2][row] = v.z; As[kq + 3][row] = v.w;
            float4 w = *reinterpret_cast<const float4*>(Uw + (size_t)(n0 + row) * EE + k0 + kq);
            Bs[kq + 0][row] = w.x; Bs[kq + 1][row] = w.y;
            Bs[kq + 2][row] = w.z; Bs[kq + 3][row] = w.w;
        }
        __syncthreads();
#pragma unroll
        for (int k = 0; k < 16; k++) {
            float4 a0 = *reinterpret_cast<const float4*>(&As[k][ty * 8]);
            float4 a1 = *reinterpret_cast<const float4*>(&As[k][ty * 8 + 4]);
            float4 b0 = *reinterpret_cast<const float4*>(&Bs[k][tx * 8]);
            float4 b1 = *reinterpret_cast<const float4*>(&Bs[k][tx * 8 + 4]);
            float av[8] = {a0.x, a0.y, a0.z, a0.w, a1.x, a1.y, a1.z, a1.w};
            float bv[8] = {b0.x, b0.y, b0.z, b0.w, b1.x, b1.y, b1.z, b1.w};
#pragma unroll
            for (int mi = 0; mi < 8; mi++)
#pragma unroll
                for (int ni = 0; ni < 8; ni++) acc[mi][ni] += av[mi] * bv[ni];
        }
        __syncthreads();
    }

#pragma unroll
    for (int mi = 0; mi < 8; mi++) {
        int m = m0 + ty * 8 + mi;
        float* dst = g_uproj + (size_t)m * GG + n0 + tx * 8;
#pragma unroll
        for (int ni = 0; ni < 8; ni++) {
            int g = n0 + tx * 8 + ni;
            dst[ni] = acc[mi][ni] + Ub[g] + Wab[g];
        }
    }
}

// ---------------- persistent scan kernel ----------------
__device__ __forceinline__ float sigmoidf_(float x) { return 1.0f / (1.0f + expf(-x)); }

__global__ __launch_bounds__(NTHR, 2) void scan_kernel(
    const float* __restrict__ ts,    // [B, S]
    const float* __restrict__ Wall,  // [G, H]
    const float* __restrict__ Wd,    // [H, H]
    const float* __restrict__ Wdb,   // [H]
    float* __restrict__ out)         // [B*S*H + 2*B*H]
{
    __shared__ float As[32][68];
    __shared__ float Ws[32][68];
    __shared__ int   s_t;

    const int tid  = threadIdx.x;
    const int gtid = blockIdx.x * NTHR + tid;
    const int ty = tid >> 4;   // 0..7  (8 rows each)
    const int tx = tid & 15;   // 0..15 (4 cols each)

    // init h, c
    for (int i = gtid; i < BB * HH; i += NB * NTHR) { g_h[i] = 0.0f; g_c[i] = 0.0f; }
    gsync();

    for (int s = 0; s < SS; s++) {
        // ---- Phase G: work-stealing split-K GEMM ----
        const unsigned base = (unsigned)s * (NTASK + NB);
        while (true) {
            if (tid == 0) s_t = (int)(atomicAdd(&g_task, 1u) - base);
            __syncthreads();
            const int t = s_t;
            if (t >= NTASK) break;

            const int nt = t % NT;          // 0..39
            const int ks = t / NT;          // 0..15
            const int k0 = ks * 32;
            const float* A  = (nt < 32) ? g_h : g_c;
            const float* Wp = (nt < 32) ? (Wall + (size_t)(nt * 64) * HH)
                                        : (Wd   + (size_t)((nt - 32) * 64) * HH);

            // load A tile (64 rows x 32 k) and W tile (64 rows x 32 k): 4 float4 each
#pragma unroll
            for (int r = 0; r < 4; r++) {
                int lin = tid + r * NTHR;        // 0..511
                int row = lin >> 3;              // 0..63
                int kq  = (lin & 7) << 2;        // 0,4,...,28
                float4 v = *reinterpret_cast<const float4*>(A + (size_t)row * HH + k0 + kq);
                As[kq + 0][row] = v.x; As[kq + 1][row] = v.y;
                As[kq + 2][row] = v.z; As[kq + 3][row] = v.w;
                float4 w = *reinterpret_cast<const float4*>(Wp + (size_t)row * HH + k0 + kq);
                Ws[kq + 0][row] = w.x; Ws[kq + 1][row] = w.y;
                Ws[kq + 2][row] = w.z; Ws[kq + 3][row] = w.w;
            }
            __syncthreads();

            float acc[8][4];
#pragma unroll
            for (int i = 0; i < 8; i++)
#pragma unroll
                for (int j = 0; j < 4; j++) acc[i][j] = 0.0f;

#pragma unroll
            for (int k = 0; k < 32; k++) {
                float4 a0 = *reinterpret_cast<const float4*>(&As[k][ty * 8]);
                float4 a1 = *reinterpret_cast<const float4*>(&As[k][ty * 8 + 4]);
                float4 b  = *reinterpret_cast<const float4*>(&Ws[k][tx * 4]);
                float av[8] = {a0.x, a0.y, a0.z, a0.w, a1.x, a1.y, a1.z, a1.w};
                float bv[4] = {b.x, b.y, b.z, b.w};
#pragma unroll
                for (int mi = 0; mi < 8; mi++)
#pragma unroll
                    for (int ni = 0; ni < 4; ni++) acc[mi][ni] += av[mi] * bv[ni];
            }
            __syncthreads();   // protect As/Ws + s_t for next iteration

            // store deterministic partials
            float* pb = g_part + (size_t)ks * BB * NTOT;
            const int col = nt * 64 + tx * 4;
#pragma unroll
            for (int mi = 0; mi < 8; mi++) {
                int m = ty * 8 + mi;
                *reinterpret_cast<float4*>(pb + (size_t)m * NTOT + col) =
                    make_float4(acc[mi][0], acc[mi][1], acc[mi][2], acc[mi][3]);
            }
        }
        gsync();

        // ---- Phase E: split-K reduce + gates + state update ----
        if (gtid < BB * HH) {
            const int b = gtid >> 9;
            const int j = gtid & 511;

            float aF = 0.f, aI = 0.f, aO = 0.f, aC = 0.f, aD = 0.f;
#pragma unroll
            for (int ksl = 0; ksl < KS; ksl++) {
                const float* p = g_part + (size_t)ksl * BB * NTOT + (size_t)b * NTOT;
                aF += p[j];
                aI += p[512 + j];
                aO += p[1024 + j];
                aC += p[1536 + j];
                aD += p[2048 + j];
            }

            const float* u = g_uproj + ((size_t)b * SS + s) * GG;
            float preF = aF + u[j];
            float preI = aI + u[512 + j];
            float preO = aO + u[1024 + j];
            float preC = aC + u[1536 + j];

            float cs1  = tanhf(aD + Wdb[j]);
            float dec  = 1.0f / logf(2.71828182845904523536f + ts[b * SS + s]);
            float cold = g_c[gtid];
            float cadj = (cold - cs1) + cs1 * dec;

            float f  = sigmoidf_(preF);
            float i_ = sigmoidf_(preI);
            float o  = sigmoidf_(preO);
            float ct = tanhf(preC);

            float cn = f * cadj + i_ * ct;
            float hn = o * tanhf(cn);

            g_c[gtid] = cn;
            g_h[gtid] = hn;
            out[((size_t)b * SS + s) * HH + j] = hn;
        }
        gsync();
    }

    // finalize: h_f, c_f
    for (int i = gtid; i < BB * HH; i += NB * NTHR) {
        out[(size_t)BB * SS * HH + i]           = g_h[i];
        out[(size_t)BB * SS * HH + BB * HH + i] = g_c[i];
    }
    if (gtid == 0) g_task = 0;   // replay determinism
}

// ---------------- launch ----------------
extern "C" void kernel_launch(void* const* d_in, const int* in_sizes, int n_in,
                              void* d_out, int out_size) {
    const float* inputs = (const float*)d_in[0];   // [B,S,E]
    const float* tstamp = (const float*)d_in[1];   // [B,S]
    const float* Wall_w = (const float*)d_in[2];   // [4H,H]
    const float* Wall_b = (const float*)d_in[3];   // [4H]
    const float* U_w    = (const float*)d_in[4];   // [4H,E]
    const float* U_b    = (const float*)d_in[5];   // [4H]
    const float* Wd_w   = (const float*)d_in[6];   // [H,H]
    const float* Wd_b   = (const float*)d_in[7];   // [H]
    float* out = (float*)d_out;

    dim3 gu(BB * SS / 128, GG / 128);              // 256 x 16
    uproj_kernel<<<gu, 256>>>(inputs, U_w, U_b, Wall_b);

    scan_kernel<<<NB, NTHR>>>(tstamp, Wall_w, Wd_w, Wd_b, out);
}

// round 5
// speedup vs baseline: 1.5249x; 1.5249x over previous
#include <cuda_runtime.h>
#include <cmath>

// Problem constants
#define BB   64     // batch
#define SS   512    // seq
#define EE   256    // embed
#define HH   512    // hidden
#define GG   2048   // 4*H
#define NTOT 2560   // GG + HH

// Persistent-kernel geometry: 296 blocks = 8 K-slices x 37 col-tiles
#define NB     296
#define NTHR   128
#define KS     8      // K slices of 64
#define NTILE  37     // col tiles: 30 gate tiles (68/69) + 7 Wd tiles (73/74)
#define WMAX   80     // padded col width (16 tx * 5 cols)

// ---------------- device scratch ----------------
__device__ float g_uproj[(size_t)BB * SS * GG];          // 256 MB
__device__ float g_h[BB * HH];
__device__ float g_c[BB * HH];
__device__ float g_part[(size_t)KS * BB * NTOT];         // 5.25 MB

__device__ unsigned g_count = 0;   // barrier arrivals (self-resetting)
__device__ unsigned g_gen   = 0;   // barrier generation (monotonic)

// ---------------- grid-wide barrier ----------------
__device__ __forceinline__ void gsync() {
    __syncthreads();
    if (threadIdx.x == 0) {
        __threadfence();
        unsigned gen = *(volatile unsigned*)&g_gen;
        __threadfence();
        if (atomicAdd(&g_count, 1u) == NB - 1u) {
            g_count = 0;
            __threadfence();
            atomicAdd(&g_gen, 1u);
        } else {
            while (*(volatile unsigned*)&g_gen == gen) __nanosleep(32);
        }
        __threadfence();
    }
    __syncthreads();
}

// ---------------- u_proj GEMM (unchanged, worked) ----------------
__global__ __launch_bounds__(256) void uproj_kernel(
    const float* __restrict__ inp, const float* __restrict__ Uw,
    const float* __restrict__ Ub,  const float* __restrict__ Wab)
{
    __shared__ float As[16][132];
    __shared__ float Bs[16][132];
    const int bm = blockIdx.x, bn = blockIdx.y, tid = threadIdx.x;
    const int tx = tid & 15, ty = tid >> 4;

    float acc[8][8];
#pragma unroll
    for (int i = 0; i < 8; i++)
#pragma unroll
        for (int j = 0; j < 8; j++) acc[i][j] = 0.0f;

    const int m0 = bm * 128, n0 = bn * 128;
    for (int k0 = 0; k0 < EE; k0 += 16) {
#pragma unroll
        for (int i = 0; i < 2; i++) {
            int idx = tid + i * 256;
            int row = idx >> 2, kq = (idx & 3) << 2;
            float4 v = *reinterpret_cast<const float4*>(inp + (size_t)(m0 + row) * EE + k0 + kq);
            As[kq + 0][row] = v.x; As[kq + 1][row] = v.y; As[kq + 2][row] = v.z; As[kq + 3][row] = v.w;
            float4 w = *reinterpret_cast<const float4*>(Uw + (size_t)(n0 + row) * EE + k0 + kq);
            Bs[kq + 0][row] = w.x; Bs[kq + 1][row] = w.y; Bs[kq + 2][row] = w.z; Bs[kq + 3][row] = w.w;
        }
        __syncthreads();
#pragma unroll
        for (int k = 0; k < 16; k++) {
            float4 a0 = *reinterpret_cast<const float4*>(&As[k][ty * 8]);
            float4 a1 = *reinterpret_cast<const float4*>(&As[k][ty * 8 + 4]);
            float4 b0 = *reinterpret_cast<const float4*>(&Bs[k][tx * 8]);
            float4 b1 = *reinterpret_cast<const float4*>(&Bs[k][tx * 8 + 4]);
            float av[8] = {a0.x, a0.y, a0.z, a0.w, a1.x, a1.y, a1.z, a1.w};
            float bv[8] = {b0.x, b0.y, b0.z, b0.w, b1.x, b1.y, b1.z, b1.w};
#pragma unroll
            for (int mi = 0; mi < 8; mi++)
#pragma unroll
                for (int ni = 0; ni < 8; ni++) acc[mi][ni] += av[mi] * bv[ni];
        }
        __syncthreads();
    }
#pragma unroll
    for (int mi = 0; mi < 8; mi++) {
        int m = m0 + ty * 8 + mi;
        float* dst = g_uproj + (size_t)m * GG + n0 + tx * 8;
#pragma unroll
        for (int ni = 0; ni < 8; ni++) {
            int g = n0 + tx * 8 + ni;
            dst[ni] = acc[mi][ni] + Ub[g] + Wab[g];
        }
    }
}

// ---------------- persistent weight-stationary scan ----------------
__device__ __forceinline__ float sigmoidf_(float x) { return 1.0f / (1.0f + expf(-x)); }

__global__ __launch_bounds__(NTHR, 2) void scan_kernel(
    const float* __restrict__ ts,    // [B, S]
    const float* __restrict__ Wall,  // [G, H]
    const float* __restrict__ Wd,    // [H, H]
    const float* __restrict__ Wdb,   // [H]
    float* __restrict__ out)
{
    __shared__ float Ws[64][WMAX];   // weight tile [k][col], zero-padded: 20.5 KB
    __shared__ float As[64][68];     // A tile [k][b]: 17.4 KB

    const int tid  = threadIdx.x;
    const int gtid = blockIdx.x * NTHR + tid;
    const int ty = tid >> 4;    // 0..7  : 8 batches each
    const int tx = tid & 15;    // 0..15 : 5 cols each

    // --- block's fixed tile: kslice q, col tile ct ---
    const int q  = blockIdx.x / NTILE;        // 0..7
    const int ct = blockIdx.x % NTILE;        // 0..36
    const int k0 = q * 64;
    int c0, width, isGate;
    if (ct < 30) { isGate = 1; width = 68 + (ct < 8 ? 1 : 0); c0 = ct * 68 + min(ct, 8); }
    else         { int j = ct - 30; isGate = 0; width = 73 + (j < 1 ? 1 : 0); c0 = 2048 + j * 73 + min(j, 1); }

    // --- one-time: zero-pad + load weight tile into smem ---
    for (int i = tid; i < 64 * WMAX; i += NTHR) ((float*)Ws)[i] = 0.0f;
    __syncthreads();
    for (int lin = tid; lin < width * 16; lin += NTHR) {
        int col = lin >> 4, kq4 = (lin & 15) << 2;
        int row = c0 + col;
        const float* wr = isGate ? (Wall + (size_t)row * HH) : (Wd + (size_t)(row - 2048) * HH);
        float4 v = *reinterpret_cast<const float4*>(wr + k0 + kq4);
        Ws[kq4 + 0][col] = v.x; Ws[kq4 + 1][col] = v.y;
        Ws[kq4 + 2][col] = v.z; Ws[kq4 + 3][col] = v.w;
    }

    // init h, c
    for (int i = gtid; i < BB * HH; i += NB * NTHR) { g_h[i] = 0.0f; g_c[i] = 0.0f; }
    gsync();

    const float* Asrc = isGate ? g_h : g_c;

    for (int s = 0; s < SS; s++) {
        // ---- load A slice [64 b x 64 k] -> As[k][b] ----
#pragma unroll
        for (int i = 0; i < 8; i++) {
            int lin = tid + i * NTHR;          // 0..1023
            int b = lin >> 4, kq4 = (lin & 15) << 2;
            float4 v = *reinterpret_cast<const float4*>(Asrc + (size_t)b * HH + k0 + kq4);
            As[kq4 + 0][b] = v.x; As[kq4 + 1][b] = v.y;
            As[kq4 + 2][b] = v.z; As[kq4 + 3][b] = v.w;
        }
        __syncthreads();

        // ---- dense 64 x 80 x 64 GEMM from smem ----
        float acc[8][5];
#pragma unroll
        for (int i = 0; i < 8; i++)
#pragma unroll
            for (int j = 0; j < 5; j++) acc[i][j] = 0.0f;

#pragma unroll
        for (int k = 0; k < 64; k++) {
            float4 a0 = *reinterpret_cast<const float4*>(&As[k][ty * 8]);
            float4 a1 = *reinterpret_cast<const float4*>(&As[k][ty * 8 + 4]);
            const float* wr = &Ws[k][tx * 5];
            float w0 = wr[0], w1 = wr[1], w2 = wr[2], w3 = wr[3], w4 = wr[4];
            float av[8] = {a0.x, a0.y, a0.z, a0.w, a1.x, a1.y, a1.z, a1.w};
#pragma unroll
            for (int mi = 0; mi < 8; mi++) {
                acc[mi][0] += av[mi] * w0;
                acc[mi][1] += av[mi] * w1;
                acc[mi][2] += av[mi] * w2;
                acc[mi][3] += av[mi] * w3;
                acc[mi][4] += av[mi] * w4;
            }
        }

        // ---- store deterministic partials ----
        {
            float* pb = g_part + (size_t)q * BB * NTOT + c0 + tx * 5;
            const int rem = width - tx * 5;    // may be <=0 for pad threads
#pragma unroll
            for (int mi = 0; mi < 8; mi++) {
                int b = ty * 8 + mi;
                float* dst = pb + (size_t)b * NTOT;
#pragma unroll
                for (int j = 0; j < 5; j++)
                    if (j < rem) dst[j] = acc[mi][j];
            }
        }
        __syncthreads();   // As reused next step only after gsyncs, but keep tile coherent
        gsync();

        // ---- epilogue: split-K reduce + gates + state update ----
        if (gtid < BB * HH) {
            const int b = gtid >> 9;
            const int j = gtid & 511;

            float aF = 0.f, aI = 0.f, aO = 0.f, aC = 0.f, aD = 0.f;
#pragma unroll
            for (int ksl = 0; ksl < KS; ksl++) {
                const float* p = g_part + (size_t)ksl * BB * NTOT + (size_t)b * NTOT;
                aF += p[j];
                aI += p[512 + j];
                aO += p[1024 + j];
                aC += p[1536 + j];
                aD += p[2048 + j];
            }

            const float* u = g_uproj + ((size_t)b * SS + s) * GG;
            float preF = aF + u[j];
            float preI = aI + u[512 + j];
            float preO = aO + u[1024 + j];
            float preC = aC + u[1536 + j];

            float cs1  = tanhf(aD + Wdb[j]);
            float dec  = 1.0f / logf(2.71828182845904523536f + ts[b * SS + s]);
            float cold = g_c[gtid];
            float cadj = (cold - cs1) + cs1 * dec;

            float f  = sigmoidf_(preF);
            float i_ = sigmoidf_(preI);
            float o  = sigmoidf_(preO);
            float ct_ = tanhf(preC);

            float cn = f * cadj + i_ * ct_;
            float hn = o * tanhf(cn);

            g_c[gtid] = cn;
            g_h[gtid] = hn;
            out[((size_t)b * SS + s) * HH + j] = hn;
        }
        gsync();
    }

    // finalize: h_f, c_f
    for (int i = gtid; i < BB * HH; i += NB * NTHR) {
        out[(size_t)BB * SS * HH + i]           = g_h[i];
        out[(size_t)BB * SS * HH + BB * HH + i] = g_c[i];
    }
}

// ---------------- launch ----------------
extern "C" void kernel_launch(void* const* d_in, const int* in_sizes, int n_in,
                              void* d_out, int out_size) {
    const float* inputs = (const float*)d_in[0];
    const float* tstamp = (const float*)d_in[1];
    const float* Wall_w = (const float*)d_in[2];
    const float* Wall_b = (const float*)d_in[3];
    const float* U_w    = (const float*)d_in[4];
    const float* U_b    = (const float*)d_in[5];
    const float* Wd_w   = (const float*)d_in[6];
    const float* Wd_b   = (const float*)d_in[7];
    float* out = (float*)d_out;

    dim3 gu(BB * SS / 128, GG / 128);
    uproj_kernel<<<gu, 256>>>(inputs, U_w, U_b, Wall_b);

    scan_kernel<<<NB, NTHR>>>(tstamp, Wall_w, Wd_w, Wd_b, out);
}

// round 6
// speedup vs baseline: 1.6458x; 1.0793x over previous
#include <cuda_runtime.h>
#include <cmath>

// Problem constants
#define BB   64
#define SS   512
#define EE   256
#define HH   512
#define GG   2048
#define NTOT 2560   // GG + HH

// Persistent geometry: 296 blocks = 8 K-slices x 37 col-tiles
#define NB     296
#define NTHR   128
#define KS     8      // K slices of 64
#define NTILE  37     // 30 gate tiles (68/69) + 7 Wd tiles (73/74)
#define WMAX   80     // padded col width (16 tx * 5)

typedef unsigned long long ull;

// packed f32x2 FMA: d = a*b + d (per 32-bit lane)
#define FMA2(d, a, b) asm("fma.rn.f32x2 %0, %1, %2, %0;" : "+l"(d) : "l"(a), "l"(b))

__device__ __forceinline__ void unpack2(ull v, float& lo, float& hi) {
    asm("mov.b64 {%0, %1}, %2;" : "=f"(lo), "=f"(hi) : "l"(v));
}

// ---------------- device scratch ----------------
__device__ float g_uproj[(size_t)BB * SS * GG];          // 256 MB
__device__ float g_h[BB * HH];
__device__ float g_c[BB * HH];
__device__ float g_part[(size_t)KS * BB * NTOT];         // 5.25 MB

__device__ unsigned g_count = 0;
__device__ unsigned g_gen   = 0;

// ---------------- grid-wide barrier ----------------
__device__ __forceinline__ void gsync() {
    __syncthreads();
    if (threadIdx.x == 0) {
        unsigned gen = *(volatile unsigned*)&g_gen;
        __threadfence();
        if (atomicAdd(&g_count, 1u) == NB - 1u) {
            g_count = 0;
            __threadfence();
            atomicAdd(&g_gen, 1u);
        } else {
            while (*(volatile unsigned*)&g_gen == gen) {}
        }
        __threadfence();
    }
    __syncthreads();
}

// ---------------- u_proj GEMM with FFMA2 (col-pair packing) ----------------
__global__ __launch_bounds__(256, 2) void uproj_kernel(
    const float* __restrict__ inp, const float* __restrict__ Uw,
    const float* __restrict__ Ub,  const float* __restrict__ Wab)
{
    __shared__ __align__(16) float2 As2[16][132];  // (a,a) dup per (k,m)
    __shared__ __align__(16) float  Bs[16][132];   // plain w

    const int bm = blockIdx.x, bn = blockIdx.y, tid = threadIdx.x;
    const int tx = tid & 15, ty = tid >> 4;

    ull acc[8][4];
#pragma unroll
    for (int i = 0; i < 8; i++)
#pragma unroll
        for (int j = 0; j < 4; j++) acc[i][j] = 0ull;

    const int m0 = bm * 128, n0 = bn * 128;
    for (int k0 = 0; k0 < EE; k0 += 16) {
#pragma unroll
        for (int i = 0; i < 2; i++) {
            int idx = tid + i * 256;
            int row = idx >> 2, kq = (idx & 3) << 2;
            float4 v = *reinterpret_cast<const float4*>(inp + (size_t)(m0 + row) * EE + k0 + kq);
            As2[kq + 0][row] = make_float2(v.x, v.x);
            As2[kq + 1][row] = make_float2(v.y, v.y);
            As2[kq + 2][row] = make_float2(v.z, v.z);
            As2[kq + 3][row] = make_float2(v.w, v.w);
            float4 w = *reinterpret_cast<const float4*>(Uw + (size_t)(n0 + row) * EE + k0 + kq);
            Bs[kq + 0][row] = w.x; Bs[kq + 1][row] = w.y;
            Bs[kq + 2][row] = w.z; Bs[kq + 3][row] = w.w;
        }
        __syncthreads();
#pragma unroll
        for (int k = 0; k < 16; k++) {
            // a-dup pairs (broadcast across tx lanes)
            ulonglong2 A01 = *reinterpret_cast<const ulonglong2*>(&As2[k][ty * 8 + 0]);
            ulonglong2 A23 = *reinterpret_cast<const ulonglong2*>(&As2[k][ty * 8 + 2]);
            ulonglong2 A45 = *reinterpret_cast<const ulonglong2*>(&As2[k][ty * 8 + 4]);
            ulonglong2 A67 = *reinterpret_cast<const ulonglong2*>(&As2[k][ty * 8 + 6]);
            ull av[8] = {A01.x, A01.y, A23.x, A23.y, A45.x, A45.y, A67.x, A67.y};
            // w natural col-pairs
            ulonglong2 W01 = *reinterpret_cast<const ulonglong2*>(&Bs[k][tx * 8]);
            ulonglong2 W23 = *reinterpret_cast<const ulonglong2*>(&Bs[k][tx * 8 + 4]);
            ull wv[4] = {W01.x, W01.y, W23.x, W23.y};
#pragma unroll
            for (int mi = 0; mi < 8; mi++)
#pragma unroll
                for (int nc = 0; nc < 4; nc++) FMA2(acc[mi][nc], av[mi], wv[nc]);
        }
        __syncthreads();
    }
#pragma unroll
    for (int mi = 0; mi < 8; mi++) {
        int m = m0 + ty * 8 + mi;
        float* dst = g_uproj + (size_t)m * GG + n0 + tx * 8;
#pragma unroll
        for (int nc = 0; nc < 4; nc++) {
            float lo, hi;
            unpack2(acc[mi][nc], lo, hi);
            int g = n0 + tx * 8 + nc * 2;
            dst[nc * 2 + 0] = lo + Ub[g]     + Wab[g];
            dst[nc * 2 + 1] = hi + Ub[g + 1] + Wab[g + 1];
        }
    }
}

// ---------------- persistent weight-stationary scan (FFMA2 batch-pairs) ----------------
__device__ __forceinline__ float sigmoidf_(float x) { return 1.0f / (1.0f + expf(-x)); }

#define SMEM_WS2 0
#define SMEM_AS  (64 * WMAX * 8)                 // 40960
#define SMEM_TOT (SMEM_AS + 64 * 68 * 4)         // 58368

__global__ __launch_bounds__(NTHR, 2) void scan_kernel(
    const float* __restrict__ ts,
    const float* __restrict__ Wall,
    const float* __restrict__ Wd,
    const float* __restrict__ Wdb,
    float* __restrict__ out)
{
    extern __shared__ __align__(16) char smem[];
    float2 (*Ws2)[WMAX] = reinterpret_cast<float2(*)[WMAX]>(smem + SMEM_WS2);  // (w,w) dup
    float  (*As)[68]    = reinterpret_cast<float(*)[68]>(smem + SMEM_AS);      // [k][b]

    const int tid  = threadIdx.x;
    const int gtid = blockIdx.x * NTHR + tid;
    const int ty = tid >> 4;    // 0..7  : 4 batch-pairs
    const int tx = tid & 15;    // 0..15 : 5 cols

    const int q  = blockIdx.x / NTILE;
    const int ct = blockIdx.x % NTILE;
    const int k0 = q * 64;
    int c0, width, isGate;
    if (ct < 30) { isGate = 1; width = 68 + (ct < 8 ? 1 : 0); c0 = ct * 68 + min(ct, 8); }
    else         { int j = ct - 30; isGate = 0; width = 73 + (j < 1 ? 1 : 0); c0 = 2048 + j * 73 + min(j, 1); }

    // one-time: zero-pad + load duplicated weight tile
    for (int i = tid; i < 64 * WMAX; i += NTHR)
        reinterpret_cast<float2*>(smem)[i] = make_float2(0.f, 0.f);
    __syncthreads();
    for (int lin = tid; lin < width * 16; lin += NTHR) {
        int col = lin >> 4, kq4 = (lin & 15) << 2;
        int row = c0 + col;
        const float* wr = isGate ? (Wall + (size_t)row * HH) : (Wd + (size_t)(row - 2048) * HH);
        float4 v = *reinterpret_cast<const float4*>(wr + k0 + kq4);
        Ws2[kq4 + 0][col] = make_float2(v.x, v.x);
        Ws2[kq4 + 1][col] = make_float2(v.y, v.y);
        Ws2[kq4 + 2][col] = make_float2(v.z, v.z);
        Ws2[kq4 + 3][col] = make_float2(v.w, v.w);
    }

    for (int i = gtid; i < BB * HH; i += NB * NTHR) { g_h[i] = 0.0f; g_c[i] = 0.0f; }
    gsync();

    const float* Asrc = isGate ? g_h : g_c;

    for (int s = 0; s < SS; s++) {
        // ---- load A slice [64 b x 64 k] -> As[k][b] ----
#pragma unroll
        for (int i = 0; i < 8; i++) {
            int lin = tid + i * NTHR;
            int b = lin >> 4, kq4 = (lin & 15) << 2;
            float4 v = *reinterpret_cast<const float4*>(Asrc + (size_t)b * HH + k0 + kq4);
            As[kq4 + 0][b] = v.x; As[kq4 + 1][b] = v.y;
            As[kq4 + 2][b] = v.z; As[kq4 + 3][b] = v.w;
        }
        __syncthreads();

        // ---- 64 x 80 x 64 GEMM, packed batch-pairs ----
        ull acc[4][5];
#pragma unroll
        for (int i = 0; i < 4; i++)
#pragma unroll
            for (int j = 0; j < 5; j++) acc[i][j] = 0ull;

#pragma unroll 16
        for (int k = 0; k < 64; k++) {
            // batch pairs (broadcast across tx): 2x LDS.128 = 4 pairs
            ulonglong2 Aa = *reinterpret_cast<const ulonglong2*>(&As[k][ty * 8]);
            ulonglong2 Ab = *reinterpret_cast<const ulonglong2*>(&As[k][ty * 8 + 4]);
            ull ap[4] = {Aa.x, Aa.y, Ab.x, Ab.y};
            // duplicated weights: 5x LDS.64
            const ull* wr = reinterpret_cast<const ull*>(&Ws2[k][tx * 5]);
            ull w0 = wr[0], w1 = wr[1], w2 = wr[2], w3 = wr[3], w4 = wr[4];
#pragma unroll
            for (int p = 0; p < 4; p++) {
                FMA2(acc[p][0], ap[p], w0);
                FMA2(acc[p][1], ap[p], w1);
                FMA2(acc[p][2], ap[p], w2);
                FMA2(acc[p][3], ap[p], w3);
                FMA2(acc[p][4], ap[p], w4);
            }
        }

        // ---- store deterministic partials ----
        {
            const int rem = width - tx * 5;
            float* pb = g_part + (size_t)q * BB * NTOT + c0 + tx * 5;
#pragma unroll
            for (int p = 0; p < 4; p++) {
                float* d0 = pb + (size_t)(ty * 8 + 2 * p) * NTOT;
                float* d1 = d0 + NTOT;
#pragma unroll
                for (int j = 0; j < 5; j++) {
                    if (j < rem) {
                        float lo, hi;
                        unpack2(acc[p][j], lo, hi);
                        d0[j] = lo;
                        d1[j] = hi;
                    }
                }
            }
        }
        gsync();

        // ---- epilogue (float2-vectorized): reduce + gates + state update ----
        if (gtid < BB * HH / 2) {
            const int b  = gtid >> 8;
            const int j2 = gtid & 255;     // float2 index within 512

            float2 aF = {0.f,0.f}, aI = {0.f,0.f}, aO = {0.f,0.f}, aC = {0.f,0.f}, aD = {0.f,0.f};
#pragma unroll
            for (int ksl = 0; ksl < KS; ksl++) {
                const float2* p = reinterpret_cast<const float2*>(g_part + (size_t)ksl * BB * NTOT + (size_t)b * NTOT);
                float2 v;
                v = p[j2];        aF.x += v.x; aF.y += v.y;
                v = p[256 + j2];  aI.x += v.x; aI.y += v.y;
                v = p[512 + j2];  aO.x += v.x; aO.y += v.y;
                v = p[768 + j2];  aC.x += v.x; aC.y += v.y;
                v = p[1024 + j2]; aD.x += v.x; aD.y += v.y;
            }

            const float2* u = reinterpret_cast<const float2*>(g_uproj + ((size_t)b * SS + s) * GG);
            float2 uF = u[j2], uI = u[256 + j2], uO = u[512 + j2], uC = u[768 + j2];
            const float2* wdb2 = reinterpret_cast<const float2*>(Wdb);
            float2 wb = wdb2[j2];
            float dec = 1.0f / logf(2.71828182845904523536f + ts[b * SS + s]);
            float2 cold = reinterpret_cast<const float2*>(g_c)[gtid];

            float cn0, hn0, cn1, hn1;
            {
                float cs1 = tanhf(aD.x + wb.x);
                float cadj = (cold.x - cs1) + cs1 * dec;
                float f  = sigmoidf_(aF.x + uF.x);
                float i_ = sigmoidf_(aI.x + uI.x);
                float o  = sigmoidf_(aO.x + uO.x);
                float ctl = tanhf(aC.x + uC.x);
                cn0 = f * cadj + i_ * ctl;
                hn0 = o * tanhf(cn0);
            }
            {
                float cs1 = tanhf(aD.y + wb.y);
                float cadj = (cold.y - cs1) + cs1 * dec;
                float f  = sigmoidf_(aF.y + uF.y);
                float i_ = sigmoidf_(aI.y + uI.y);
                float o  = sigmoidf_(aO.y + uO.y);
                float ctl = tanhf(aC.y + uC.y);
                cn1 = f * cadj + i_ * ctl;
                hn1 = o * tanhf(cn1);
            }

            reinterpret_cast<float2*>(g_c)[gtid] = make_float2(cn0, cn1);
            reinterpret_cast<float2*>(g_h)[gtid] = make_float2(hn0, hn1);
            reinterpret_cast<float2*>(out)[((size_t)b * SS + s) * (HH / 2) + j2] = make_float2(hn0, hn1);
        }
        gsync();
    }

    for (int i = gtid; i < BB * HH; i += NB * NTHR) {
        out[(size_t)BB * SS * HH + i]           = g_h[i];
        out[(size_t)BB * SS * HH + BB * HH + i] = g_c[i];
    }
}

// ---------------- launch ----------------
extern "C" void kernel_launch(void* const* d_in, const int* in_sizes, int n_in,
                              void* d_out, int out_size) {
    const float* inputs = (const float*)d_in[0];
    const float* tstamp = (const float*)d_in[1];
    const float* Wall_w = (const float*)d_in[2];
    const float* Wall_b = (const float*)d_in[3];
    const float* U_w    = (const float*)d_in[4];
    const float* U_b    = (const float*)d_in[5];
    const float* Wd_w   = (const float*)d_in[6];
    const float* Wd_b   = (const float*)d_in[7];
    float* out = (float*)d_out;

    static int smem_set = 0;
    if (!smem_set) {
        cudaFuncSetAttribute(scan_kernel, cudaFuncAttributeMaxDynamicSharedMemorySize, SMEM_TOT);
        smem_set = 1;
    }

    dim3 gu(BB * SS / 128, GG / 128);
    uproj_kernel<<<gu, 256>>>(inputs, U_w, U_b, Wall_b);

    scan_kernel<<<NB, NTHR, SMEM_TOT>>>(tstamp, Wall_w, Wd_w, Wd_b, out);
}